// round 1
// baseline (speedup 1.0000x reference)
#include <cuda_runtime.h>
#include <math.h>

#define BB  2
#define SS  2048
#define DD  1024
#define HH  16
#define MMEM 4
#define HDD 64
#define NTOK (BB*SS)            // 4096
#define QCOL_ELEMS (BB*HH*SS*HDD)  // 4194304

// Scratch (allocation-free rule: __device__ globals)
__device__ float g_qrow[BB*HH*SS*HDD];   // q_row in (B,H,S,HD) layout
__device__ float g_merged[BB*SS*DD];     // context merged back to (B,S,D)

__device__ __forceinline__ float gelu_exact(float v) {
    return 0.5f * v * (1.0f + erff(v * 0.70710678118654752f));
}

// ---------------------------------------------------------------------------
// Tiled SGEMM: C[n,o] = sum_d X[n,d]*W[o,d] + bias[o]
// N = NTOK (4096), O = DD (1024), K = DD (1024)
// MODE 0: write in head-split layout (B,H,S,HD)
// MODE 1: write flat (n*DD+o) with exact GELU
// Block: 64x64 tile, 256 threads, 4x4 micro-tile per thread, BK=16.
// ---------------------------------------------------------------------------
template<int MODE>
__global__ __launch_bounds__(256) void gemm_kernel(
    const float* __restrict__ X, const float* __restrict__ W,
    const float* __restrict__ bias, float* __restrict__ C)
{
    __shared__ float As[16][64];   // [k][m]
    __shared__ float Bs[16][64];   // [k][n(out)]
    const int tid  = threadIdx.x;
    const int tx   = tid & 15;     // 0..15 (output dir)
    const int ty   = tid >> 4;     // 0..15 (token dir)
    const int n0   = blockIdx.y * 64;
    const int o0   = blockIdx.x * 64;
    const int lrow = tid >> 2;           // 0..63
    const int lf4  = (tid & 3) * 4;      // 0,4,8,12

    float acc[4][4];
    #pragma unroll
    for (int i = 0; i < 4; i++)
        #pragma unroll
        for (int j = 0; j < 4; j++) acc[i][j] = 0.0f;

    for (int k0 = 0; k0 < DD; k0 += 16) {
        float4 xa = *(const float4*)(X + (size_t)(n0 + lrow) * DD + k0 + lf4);
        float4 wa = *(const float4*)(W + (size_t)(o0 + lrow) * DD + k0 + lf4);
        __syncthreads();
        As[lf4+0][lrow] = xa.x; As[lf4+1][lrow] = xa.y;
        As[lf4+2][lrow] = xa.z; As[lf4+3][lrow] = xa.w;
        Bs[lf4+0][lrow] = wa.x; Bs[lf4+1][lrow] = wa.y;
        Bs[lf4+2][lrow] = wa.z; Bs[lf4+3][lrow] = wa.w;
        __syncthreads();
        #pragma unroll
        for (int k = 0; k < 16; k++) {
            float4 a = *(const float4*)&As[k][ty*4];
            float4 b = *(const float4*)&Bs[k][tx*4];
            acc[0][0] += a.x*b.x; acc[0][1] += a.x*b.y; acc[0][2] += a.x*b.z; acc[0][3] += a.x*b.w;
            acc[1][0] += a.y*b.x; acc[1][1] += a.y*b.y; acc[1][2] += a.y*b.z; acc[1][3] += a.y*b.w;
            acc[2][0] += a.z*b.x; acc[2][1] += a.z*b.y; acc[2][2] += a.z*b.z; acc[2][3] += a.z*b.w;
            acc[3][0] += a.w*b.x; acc[3][1] += a.w*b.y; acc[3][2] += a.w*b.z; acc[3][3] += a.w*b.w;
        }
    }

    const int ob = o0 + tx*4;
    float b0 = bias[ob+0], b1 = bias[ob+1], b2 = bias[ob+2], b3 = bias[ob+3];
    #pragma unroll
    for (int i = 0; i < 4; i++) {
        const int n = n0 + ty*4 + i;
        float4 r;
        r.x = acc[i][0] + b0; r.y = acc[i][1] + b1;
        r.z = acc[i][2] + b2; r.w = acc[i][3] + b3;
        if (MODE == 1) {
            r.x = gelu_exact(r.x); r.y = gelu_exact(r.y);
            r.z = gelu_exact(r.z); r.w = gelu_exact(r.w);
            *(float4*)(C + (size_t)n * DD + ob) = r;
        } else {
            // head-split: (b,h,s,hd); o0 is a multiple of 64 so h fixed per block col
            const int b  = n >> 11;       // n / SS
            const int s  = n & (SS - 1);
            const int h  = ob >> 6;
            const int hd = ob & 63;
            *(float4*)(C + ((size_t)((b*HH + h)*SS + s))*HDD + hd) = r;
        }
    }
}

// ---------------------------------------------------------------------------
// values = split_heads(x): pure permute, fully coalesced both sides
// ---------------------------------------------------------------------------
__global__ __launch_bounds__(256) void values_kernel(
    const float* __restrict__ x, float* __restrict__ vout)
{
    const int idx = blockIdx.x * 256 + threadIdx.x;   // over float4s
    const int t = idx * 4;
    const int hd = t & 63;
    const int s  = (t >> 6)  & (SS - 1);
    const int h  = (t >> 17) & (HH - 1);
    const int b  =  t >> 21;
    float4 v = *(const float4*)(x + ((size_t)(b*SS + s))*DD + h*HDD + hd);
    *(float4*)(vout + t) = v;
}

// ---------------------------------------------------------------------------
// Flash attention, causal, K=V source = q_row / x, plus M=4 memory slots
// folded into the same online softmax.
// Block: one (b,h,64-query tile). 256 threads; thread = (q = tid>>2, g = tid&3).
// Thread owns output dims [g*16, g*16+16) of its query and 8 keys per k-tile.
// ---------------------------------------------------------------------------
__global__ __launch_bounds__(256) void attn_kernel(
    const float* __restrict__ x,
    const float* __restrict__ past_q,
    const float* __restrict__ past_v,
    const float* __restrict__ qcol,
    const float* __restrict__ qrow,
    float* __restrict__ merged)
{
    __shared__ float Qt[HDD][68];   // [d][q], padded: 4-way instead of 32-way store conflicts
    __shared__ float Kt[HDD][36];   // [d][k], padded, 16B-aligned rows for float4 reads
    __shared__ float Vs[32][HDD];   // [k][d]
    __shared__ float Ps[32][64];    // [k][q]

    const int bh = blockIdx.y;            // 0..31
    const int b  = bh / HH;
    const int h  = bh % HH;
    const int q0 = blockIdx.x * 64;
    const int tid = threadIdx.x;
    const int q  = tid >> 2;              // 0..63
    const int g  = tid & 3;               // 0..3
    const float inv = 0.125f;             // 1/sqrt(64)

    // Load Q tile (pre-scaled)
    for (int e = tid; e < 64 * HDD; e += 256) {
        const int qq = e >> 6, d = e & 63;
        Qt[d][qq] = qrow[((size_t)bh * SS + q0 + qq) * HDD + d] * inv;
    }

    float acc[16];
    #pragma unroll
    for (int i = 0; i < 16; i++) acc[i] = 0.0f;
    float m_run = -1e30f, l_run = 0.0f;
    const int qg = q0 + q;

    const int nkt = 2 * blockIdx.x + 2;   // key tiles of 32 covering keys <= q0+63
    for (int kt = 0; kt < nkt; kt++) {
        const int k0 = kt * 32;
        __syncthreads();   // protect Vs/Ps/Kt (and Qt on first iter)
        for (int e = tid; e < 32 * HDD; e += 256) {
            const int kk = e >> 6, d = e & 63;
            Kt[d][kk] = qrow[((size_t)bh * SS + k0 + kk) * HDD + d];
            Vs[kk][d] = x[((size_t)(b * SS) + k0 + kk) * DD + h * HDD + d];
        }
        __syncthreads();

        float sc[8];
        #pragma unroll
        for (int j = 0; j < 8; j++) sc[j] = 0.0f;
        for (int d = 0; d < HDD; d++) {
            const float qv = Qt[d][q];
            float4 ka = *(const float4*)&Kt[d][g*8];
            float4 kb = *(const float4*)&Kt[d][g*8+4];
            sc[0] += qv*ka.x; sc[1] += qv*ka.y; sc[2] += qv*ka.z; sc[3] += qv*ka.w;
            sc[4] += qv*kb.x; sc[5] += qv*kb.y; sc[6] += qv*kb.z; sc[7] += qv*kb.w;
        }
        #pragma unroll
        for (int j = 0; j < 8; j++)
            if (k0 + g*8 + j > qg) sc[j] = -1e30f;

        float lm = sc[0];
        #pragma unroll
        for (int j = 1; j < 8; j++) lm = fmaxf(lm, sc[j]);
        lm = fmaxf(lm, __shfl_xor_sync(0xffffffffu, lm, 1));
        lm = fmaxf(lm, __shfl_xor_sync(0xffffffffu, lm, 2));
        const float nm = fmaxf(m_run, lm);

        float ls = 0.0f;
        #pragma unroll
        for (int j = 0; j < 8; j++) { sc[j] = __expf(sc[j] - nm); ls += sc[j]; }
        ls += __shfl_xor_sync(0xffffffffu, ls, 1);
        ls += __shfl_xor_sync(0xffffffffu, ls, 2);

        const float alpha = __expf(m_run - nm);
        l_run = l_run * alpha + ls;
        m_run = nm;
        #pragma unroll
        for (int i = 0; i < 16; i++) acc[i] *= alpha;

        #pragma unroll
        for (int j = 0; j < 8; j++) Ps[g*8 + j][q] = sc[j];
        __syncthreads();

        for (int k = 0; k < 32; k++) {
            const float pv = Ps[k][q];
            float4 va = *(const float4*)&Vs[k][g*16];
            float4 vb = *(const float4*)&Vs[k][g*16+4];
            float4 vc = *(const float4*)&Vs[k][g*16+8];
            float4 vd = *(const float4*)&Vs[k][g*16+12];
            acc[0]  += pv*va.x; acc[1]  += pv*va.y; acc[2]  += pv*va.z; acc[3]  += pv*va.w;
            acc[4]  += pv*vb.x; acc[5]  += pv*vb.y; acc[6]  += pv*vb.z; acc[7]  += pv*vb.w;
            acc[8]  += pv*vc.x; acc[9]  += pv*vc.y; acc[10] += pv*vc.z; acc[11] += pv*vc.w;
            acc[12] += pv*vd.x; acc[13] += pv*vd.y; acc[14] += pv*vd.z; acc[15] += pv*vd.w;
        }
    }

    // ---- memory slots: 4 scores per query, same softmax ----
    {
        const float* qc = qcol  + ((size_t)bh * SS + qg) * HDD;
        const float* pq = past_q + (((size_t)bh * SS + qg) * MMEM + g) * HDD;
        float ms = 0.0f;
        for (int d = 0; d < HDD; d++) ms += qc[d] * pq[d];
        ms *= inv;

        float lm = fmaxf(ms, __shfl_xor_sync(0xffffffffu, ms, 1));
        lm = fmaxf(lm, __shfl_xor_sync(0xffffffffu, lm, 2));
        const float nm = fmaxf(m_run, lm);
        const float p = __expf(ms - nm);
        float ls = p;
        ls += __shfl_xor_sync(0xffffffffu, ls, 1);
        ls += __shfl_xor_sync(0xffffffffu, ls, 2);
        const float alpha = __expf(m_run - nm);
        l_run = l_run * alpha + ls;
        #pragma unroll
        for (int i = 0; i < 16; i++) acc[i] *= alpha;

        const int base_lane = (tid & 31) & ~3;
        #pragma unroll
        for (int mm = 0; mm < MMEM; mm++) {
            const float pm = __shfl_sync(0xffffffffu, p, base_lane + mm);
            const float* pvv = past_v + (((size_t)bh * SS + qg) * MMEM + mm) * HDD + g*16;
            #pragma unroll
            for (int i = 0; i < 16; i++) acc[i] += pm * pvv[i];
        }
    }

    const float invl = 1.0f / l_run;
    float* outp = merged + ((size_t)(b * SS) + qg) * DD + h * HDD + g*16;
    #pragma unroll
    for (int i = 0; i < 16; i += 4) {
        float4 r;
        r.x = acc[i+0]*invl; r.y = acc[i+1]*invl;
        r.z = acc[i+2]*invl; r.w = acc[i+3]*invl;
        *(float4*)(outp + i) = r;
    }
}

// ---------------------------------------------------------------------------
extern "C" void kernel_launch(void* const* d_in, const int* in_sizes, int n_in,
                              void* d_out, int out_size)
{
    const float* x      = (const float*)d_in[0];
    const float* past_q = (const float*)d_in[1];
    const float* past_v = (const float*)d_in[2];
    const float* Wr     = (const float*)d_in[3];
    const float* br     = (const float*)d_in[4];
    const float* Wc     = (const float*)d_in[5];
    const float* bc     = (const float*)d_in[6];
    const float* Wo     = (const float*)d_in[7];
    const float* bo     = (const float*)d_in[8];

    float* out      = (float*)d_out;                  // (B,S,D)
    float* qcol_out = out + (size_t)BB*SS*DD;         // (B,H,S,HD)
    float* val_out  = qcol_out + (size_t)QCOL_ELEMS;  // (B,H,S,HD)

    float *qrow_ptr = nullptr, *merged_ptr = nullptr;
    cudaGetSymbolAddress((void**)&qrow_ptr, g_qrow);
    cudaGetSymbolAddress((void**)&merged_ptr, g_merged);

    dim3 gg(DD / 64, NTOK / 64);          // 16 x 64
    gemm_kernel<0><<<gg, 256>>>(x, Wr, br, qrow_ptr);
    gemm_kernel<0><<<gg, 256>>>(x, Wc, bc, qcol_out);
    values_kernel<<<QCOL_ELEMS / 4 / 256, 256>>>(x, val_out);

    dim3 ga(SS / 64, BB * HH);            // 32 x 32
    attn_kernel<<<ga, 256>>>(x, past_q, past_v, qcol_out, qrow_ptr, merged_ptr);

    gemm_kernel<1><<<gg, 256>>>(merged_ptr, Wo, bo, out);
}

// round 2
// speedup vs baseline: 3.0794x; 3.0794x over previous
#include <cuda_runtime.h>
#include <math.h>
#include <stdint.h>

#define BB 2
#define SS 2048
#define DD 1024
#define HH 16
#define MMEM 4
#define HDD 64
#define NTOK (BB*SS)
#define QCOL_ELEMS (BB*HH*SS*HDD)

__device__ float g_qrow[BB*HH*SS*HDD];   // q_row (B,H,S,HD)
__device__ float g_merged[BB*SS*DD];     // attention context (B,S,D)

__device__ __forceinline__ float gelu_exact(float v){
    return 0.5f*v*(1.0f+erff(v*0.70710678118654752f));
}
__device__ __forceinline__ unsigned tf32u(float x){
    unsigned u; asm("cvt.rna.tf32.f32 %0, %1;" : "=r"(u) : "f"(x)); return u;
}
__device__ __forceinline__ float tf32r(float x){ return __uint_as_float(tf32u(x)); }

// D(16x8) += A(16x8,row) * B(8x8,col), tf32 operands, fp32 accum
__device__ __forceinline__ void mma8(float* c, const unsigned* a, unsigned b0, unsigned b1){
    asm volatile("mma.sync.aligned.m16n8k8.row.col.f32.tf32.tf32.f32 "
        "{%0,%1,%2,%3},{%4,%5,%6,%7},{%8,%9},{%0,%1,%2,%3};"
        : "+f"(c[0]), "+f"(c[1]), "+f"(c[2]), "+f"(c[3])
        : "r"(a[0]), "r"(a[1]), "r"(a[2]), "r"(a[3]), "r"(b0), "r"(b1));
}

// ---------------------------------------------------------------------------
// TF32 MMA GEMM:  C[n,o] = sum_k X[n,k]*W[o,k] + bias[o]
// BM=BN=128, BK=16. 8 warps (2m x 4n), warp tile 64x32.
// PASSES=1: plain tf32.  PASSES=3: hi/lo split (fp32-accurate).
// MODE 0: head-split output (B,H,S,HD). MODE 1: flat + exact GELU.
// ---------------------------------------------------------------------------
#define GP 20
template<int MODE, int PASSES>
__global__ __launch_bounds__(256) void gemm_tf32(
    const float* __restrict__ X, const float* __restrict__ W,
    const float* __restrict__ bias, float* __restrict__ C)
{
    __shared__ float Ahi[128][GP], Alo[128][GP], Bhi[128][GP], Blo[128][GP];
    const int tid  = threadIdx.x;
    const int lane = tid & 31, w = tid >> 5;
    const int gid  = lane >> 2, tig = lane & 3;
    const int wm   = w >> 2, wn = w & 3;           // 2 x 4 warp grid
    const int n0   = blockIdx.y * 128, o0 = blockIdx.x * 128;
    const int lrow = tid & 127, kh = (tid >> 7) * 8;

    float c[4][4][4];
    #pragma unroll
    for (int i = 0; i < 4; i++)
        #pragma unroll
        for (int j = 0; j < 4; j++)
            #pragma unroll
            for (int q = 0; q < 4; q++) c[i][j][q] = 0.0f;

    for (int k0 = 0; k0 < DD; k0 += 16) {
        float4 xa = *(const float4*)(X + (size_t)(n0+lrow)*DD + k0 + kh);
        float4 xb = *(const float4*)(X + (size_t)(n0+lrow)*DD + k0 + kh + 4);
        float4 wa = *(const float4*)(W + (size_t)(o0+lrow)*DD + k0 + kh);
        float4 wb = *(const float4*)(W + (size_t)(o0+lrow)*DD + k0 + kh + 4);
        __syncthreads();
        {
            float xv[8] = {xa.x,xa.y,xa.z,xa.w, xb.x,xb.y,xb.z,xb.w};
            float wv[8] = {wa.x,wa.y,wa.z,wa.w, wb.x,wb.y,wb.z,wb.w};
            #pragma unroll
            for (int j = 0; j < 8; j++) {
                float hx = tf32r(xv[j]); Ahi[lrow][kh+j] = hx;
                float hw = tf32r(wv[j]); Bhi[lrow][kh+j] = hw;
                if (PASSES > 1) { Alo[lrow][kh+j] = xv[j] - hx; Blo[lrow][kh+j] = wv[j] - hw; }
            }
        }
        __syncthreads();
        #pragma unroll
        for (int kk = 0; kk < 2; kk++) {
            #pragma unroll
            for (int p = 0; p < PASSES; p++) {
                const float (*Ap)[GP] = (p == 2) ? Alo : Ahi;
                const float (*Bp)[GP] = (p == 1) ? Blo : Bhi;
                unsigned a[4][4], bb[4][2];
                #pragma unroll
                for (int mf = 0; mf < 4; mf++) {
                    const int r = wm*64 + mf*16 + gid;
                    a[mf][0] = __float_as_uint(Ap[r  ][kk*8+tig]);
                    a[mf][1] = __float_as_uint(Ap[r+8][kk*8+tig]);
                    a[mf][2] = __float_as_uint(Ap[r  ][kk*8+tig+4]);
                    a[mf][3] = __float_as_uint(Ap[r+8][kk*8+tig+4]);
                }
                #pragma unroll
                for (int nf = 0; nf < 4; nf++) {
                    const int nr = wn*32 + nf*8 + gid;
                    bb[nf][0] = __float_as_uint(Bp[nr][kk*8+tig]);
                    bb[nf][1] = __float_as_uint(Bp[nr][kk*8+tig+4]);
                }
                #pragma unroll
                for (int mf = 0; mf < 4; mf++)
                    #pragma unroll
                    for (int nf = 0; nf < 4; nf++)
                        mma8(c[mf][nf], a[mf], bb[nf][0], bb[nf][1]);
            }
        }
    }

    #pragma unroll
    for (int mf = 0; mf < 4; mf++) {
        const int r0 = n0 + wm*64 + mf*16 + gid;
        const int r1 = r0 + 8;
        #pragma unroll
        for (int nf = 0; nf < 4; nf++) {
            const int col = o0 + wn*32 + nf*8 + 2*tig;
            const float bi0 = bias[col], bi1 = bias[col+1];
            float v00 = c[mf][nf][0] + bi0, v01 = c[mf][nf][1] + bi1;
            float v10 = c[mf][nf][2] + bi0, v11 = c[mf][nf][3] + bi1;
            if (MODE == 1) {
                float2 a2 = {gelu_exact(v00), gelu_exact(v01)};
                float2 b2 = {gelu_exact(v10), gelu_exact(v11)};
                *(float2*)(C + (size_t)r0*DD + col) = a2;
                *(float2*)(C + (size_t)r1*DD + col) = b2;
            } else {
                const int hh_ = col >> 6, hd = col & 63;
                {
                    const int bi = r0 >> 11, s = r0 & (SS-1);
                    float2 a2 = {v00, v01};
                    *(float2*)(C + ((size_t)((bi*HH + hh_)*SS + s))*HDD + hd) = a2;
                }
                {
                    const int bi = r1 >> 11, s = r1 & (SS-1);
                    float2 b2 = {v10, v11};
                    *(float2*)(C + ((size_t)((bi*HH + hh_)*SS + s))*HDD + hd) = b2;
                }
            }
        }
    }
}

// ---------------------------------------------------------------------------
// values = split_heads(x)
// ---------------------------------------------------------------------------
__global__ __launch_bounds__(256) void values_kernel(
    const float* __restrict__ x, float* __restrict__ vout)
{
    const int idx = blockIdx.x * 256 + threadIdx.x;
    const int t = idx * 4;
    const int hd = t & 63;
    const int s  = (t >> 6)  & (SS - 1);
    const int h  = (t >> 17) & (HH - 1);
    const int b  =  t >> 21;
    float4 v = *(const float4*)(x + ((size_t)(b*SS + s))*DD + h*HDD + hd);
    *(float4*)(vout + t) = v;
}

// ---------------------------------------------------------------------------
// Flash attention with TF32 MMA. Q tile 128 (8 warps x m16), K/V tile 64.
// Online softmax on C fragments; P re-staged via per-warp smem; M=4 memory
// slots folded into the same softmax at the end.
// ---------------------------------------------------------------------------
#define ATTN_SMEM ((128*68 + 64*68 + 64*72 + 128*72) * 4)

__global__ __launch_bounds__(256) void attn_mma(
    const float* __restrict__ x, const float* __restrict__ past_q,
    const float* __restrict__ past_v, const float* __restrict__ qcol,
    const float* __restrict__ qrow, float* __restrict__ merged)
{
    extern __shared__ float sm[];
    float (*Qs)[68] = (float(*)[68])(sm);
    float (*Ks)[68] = (float(*)[68])(sm + 128*68);
    float (*Vs)[72] = (float(*)[72])(sm + 128*68 + 64*68);
    float (*Ps)[72] = (float(*)[72])(sm + 128*68 + 64*68 + 64*72);

    const int bh = blockIdx.y, b = bh >> 4, h = bh & 15;
    const int q0 = blockIdx.x * 128;
    const int tid = threadIdx.x, lane = tid & 31, w = tid >> 5;
    const int gid = lane >> 2, tig = lane & 3;
    const int m0 = w * 16;

    for (int e = tid; e < 128*64; e += 256) {
        int q = e >> 6, d = e & 63;
        Qs[q][d] = tf32r(qrow[((size_t)bh*SS + q0 + q)*HDD + d] * 0.125f);
    }

    float o[8][4];
    #pragma unroll
    for (int nf = 0; nf < 8; nf++)
        #pragma unroll
        for (int q = 0; q < 4; q++) o[nf][q] = 0.0f;
    float mst0 = -1e30f, mst1 = -1e30f, l0 = 0.0f, l1 = 0.0f;
    const int qg0 = q0 + m0 + gid, qg1 = qg0 + 8;
    const int nkt = 2 * blockIdx.x + 2;

    for (int kt = 0; kt < nkt; kt++) {
        const int k0 = kt * 64;
        __syncthreads();
        for (int e = tid; e < 64*64; e += 256) {
            int k = e >> 6, d = e & 63;
            Ks[k][d] = tf32r(qrow[((size_t)bh*SS + k0 + k)*HDD + d]);
            Vs[k][d] = tf32r(x[((size_t)(b*SS) + k0 + k)*DD + h*HDD + d]);
        }
        __syncthreads();

        float c[8][4];
        #pragma unroll
        for (int nf = 0; nf < 8; nf++)
            #pragma unroll
            for (int q = 0; q < 4; q++) c[nf][q] = 0.0f;

        #pragma unroll
        for (int kk = 0; kk < 8; kk++) {
            unsigned a[4];
            a[0] = __float_as_uint(Qs[m0+gid  ][kk*8+tig]);
            a[1] = __float_as_uint(Qs[m0+gid+8][kk*8+tig]);
            a[2] = __float_as_uint(Qs[m0+gid  ][kk*8+tig+4]);
            a[3] = __float_as_uint(Qs[m0+gid+8][kk*8+tig+4]);
            #pragma unroll
            for (int nf = 0; nf < 8; nf++) {
                unsigned b0 = __float_as_uint(Ks[nf*8+gid][kk*8+tig]);
                unsigned b1 = __float_as_uint(Ks[nf*8+gid][kk*8+tig+4]);
                mma8(c[nf], a, b0, b1);
            }
        }

        if (kt >= 2*(int)blockIdx.x) {  // only diagonal tiles need masking
            #pragma unroll
            for (int nf = 0; nf < 8; nf++) {
                const int kg = k0 + nf*8 + 2*tig;
                if (kg     > qg0) c[nf][0] = -1e30f;
                if (kg + 1 > qg0) c[nf][1] = -1e30f;
                if (kg     > qg1) c[nf][2] = -1e30f;
                if (kg + 1 > qg1) c[nf][3] = -1e30f;
            }
        }

        float mx0 = -1e30f, mx1 = -1e30f;
        #pragma unroll
        for (int nf = 0; nf < 8; nf++) {
            mx0 = fmaxf(mx0, fmaxf(c[nf][0], c[nf][1]));
            mx1 = fmaxf(mx1, fmaxf(c[nf][2], c[nf][3]));
        }
        mx0 = fmaxf(mx0, __shfl_xor_sync(0xffffffffu, mx0, 1));
        mx0 = fmaxf(mx0, __shfl_xor_sync(0xffffffffu, mx0, 2));
        mx1 = fmaxf(mx1, __shfl_xor_sync(0xffffffffu, mx1, 1));
        mx1 = fmaxf(mx1, __shfl_xor_sync(0xffffffffu, mx1, 2));
        const float nm0 = fmaxf(mst0, mx0), nm1 = fmaxf(mst1, mx1);

        float s0 = 0.0f, s1 = 0.0f;
        #pragma unroll
        for (int nf = 0; nf < 8; nf++) {
            c[nf][0] = __expf(c[nf][0] - nm0); s0 += c[nf][0];
            c[nf][1] = __expf(c[nf][1] - nm0); s0 += c[nf][1];
            c[nf][2] = __expf(c[nf][2] - nm1); s1 += c[nf][2];
            c[nf][3] = __expf(c[nf][3] - nm1); s1 += c[nf][3];
        }
        s0 += __shfl_xor_sync(0xffffffffu, s0, 1);
        s0 += __shfl_xor_sync(0xffffffffu, s0, 2);
        s1 += __shfl_xor_sync(0xffffffffu, s1, 1);
        s1 += __shfl_xor_sync(0xffffffffu, s1, 2);

        const float al0 = __expf(mst0 - nm0), al1 = __expf(mst1 - nm1);
        l0 = l0*al0 + s0; l1 = l1*al1 + s1; mst0 = nm0; mst1 = nm1;
        #pragma unroll
        for (int nf = 0; nf < 8; nf++) {
            o[nf][0] *= al0; o[nf][1] *= al0; o[nf][2] *= al1; o[nf][3] *= al1;
        }

        #pragma unroll
        for (int nf = 0; nf < 8; nf++) {
            Ps[m0+gid  ][nf*8+2*tig  ] = tf32r(c[nf][0]);
            Ps[m0+gid  ][nf*8+2*tig+1] = tf32r(c[nf][1]);
            Ps[m0+gid+8][nf*8+2*tig  ] = tf32r(c[nf][2]);
            Ps[m0+gid+8][nf*8+2*tig+1] = tf32r(c[nf][3]);
        }
        __syncwarp();   // P is warp-private: warp-level sync suffices

        #pragma unroll
        for (int kk = 0; kk < 8; kk++) {
            unsigned a[4];
            a[0] = __float_as_uint(Ps[m0+gid  ][kk*8+tig]);
            a[1] = __float_as_uint(Ps[m0+gid+8][kk*8+tig]);
            a[2] = __float_as_uint(Ps[m0+gid  ][kk*8+tig+4]);
            a[3] = __float_as_uint(Ps[m0+gid+8][kk*8+tig+4]);
            #pragma unroll
            for (int nf = 0; nf < 8; nf++) {
                unsigned b0 = __float_as_uint(Vs[kk*8+tig  ][nf*8+gid]);
                unsigned b1 = __float_as_uint(Vs[kk*8+tig+4][nf*8+gid]);
                mma8(o[nf], a, b0, b1);
            }
        }
    }

    // ---- memory slots: lane handles slot `tig` for its two rows ----
    {
        const float* qc0 = qcol + ((size_t)bh*SS + qg0)*HDD;
        const float* qc1 = qcol + ((size_t)bh*SS + qg1)*HDD;
        const float* pq0 = past_q + (((size_t)bh*SS + qg0)*MMEM + tig)*HDD;
        const float* pq1 = past_q + (((size_t)bh*SS + qg1)*MMEM + tig)*HDD;
        float s0 = 0.0f, s1 = 0.0f;
        #pragma unroll
        for (int d = 0; d < HDD; d += 4) {
            float4 a0 = *(const float4*)(qc0 + d), b0v = *(const float4*)(pq0 + d);
            s0 += a0.x*b0v.x + a0.y*b0v.y + a0.z*b0v.z + a0.w*b0v.w;
            float4 a1 = *(const float4*)(qc1 + d), b1v = *(const float4*)(pq1 + d);
            s1 += a1.x*b1v.x + a1.y*b1v.y + a1.z*b1v.z + a1.w*b1v.w;
        }
        s0 *= 0.125f; s1 *= 0.125f;

        float mx0 = fmaxf(s0, __shfl_xor_sync(0xffffffffu, s0, 1));
        mx0 = fmaxf(mx0, __shfl_xor_sync(0xffffffffu, mx0, 2));
        float mx1 = fmaxf(s1, __shfl_xor_sync(0xffffffffu, s1, 1));
        mx1 = fmaxf(mx1, __shfl_xor_sync(0xffffffffu, mx1, 2));
        const float nm0 = fmaxf(mst0, mx0), nm1 = fmaxf(mst1, mx1);
        const float p0 = __expf(s0 - nm0), p1 = __expf(s1 - nm1);
        float ss0 = p0, ss1 = p1;
        ss0 += __shfl_xor_sync(0xffffffffu, ss0, 1);
        ss0 += __shfl_xor_sync(0xffffffffu, ss0, 2);
        ss1 += __shfl_xor_sync(0xffffffffu, ss1, 1);
        ss1 += __shfl_xor_sync(0xffffffffu, ss1, 2);
        const float al0 = __expf(mst0 - nm0), al1 = __expf(mst1 - nm1);
        l0 = l0*al0 + ss0; l1 = l1*al1 + ss1;
        #pragma unroll
        for (int nf = 0; nf < 8; nf++) {
            o[nf][0] *= al0; o[nf][1] *= al0; o[nf][2] *= al1; o[nf][3] *= al1;
        }
        const int base = lane & ~3;
        #pragma unroll
        for (int mm = 0; mm < MMEM; mm++) {
            const float pm0 = __shfl_sync(0xffffffffu, p0, base + mm);
            const float pm1 = __shfl_sync(0xffffffffu, p1, base + mm);
            const float* v0 = past_v + (((size_t)bh*SS + qg0)*MMEM + mm)*HDD;
            const float* v1 = past_v + (((size_t)bh*SS + qg1)*MMEM + mm)*HDD;
            #pragma unroll
            for (int nf = 0; nf < 8; nf++) {
                float2 va = *(const float2*)(v0 + nf*8 + 2*tig);
                float2 vb = *(const float2*)(v1 + nf*8 + 2*tig);
                o[nf][0] += pm0*va.x; o[nf][1] += pm0*va.y;
                o[nf][2] += pm1*vb.x; o[nf][3] += pm1*vb.y;
            }
        }
    }

    const float i0 = 1.0f/l0, i1 = 1.0f/l1;
    float* ob0 = merged + ((size_t)(b*SS) + qg0)*DD + h*HDD;
    float* ob1 = merged + ((size_t)(b*SS) + qg1)*DD + h*HDD;
    #pragma unroll
    for (int nf = 0; nf < 8; nf++) {
        float2 r0 = {o[nf][0]*i0, o[nf][1]*i0};
        float2 r1 = {o[nf][2]*i1, o[nf][3]*i1};
        *(float2*)(ob0 + nf*8 + 2*tig) = r0;
        *(float2*)(ob1 + nf*8 + 2*tig) = r1;
    }
}

// ---------------------------------------------------------------------------
extern "C" void kernel_launch(void* const* d_in, const int* in_sizes, int n_in,
                              void* d_out, int out_size)
{
    const float* x      = (const float*)d_in[0];
    const float* past_q = (const float*)d_in[1];
    const float* past_v = (const float*)d_in[2];
    const float* Wr     = (const float*)d_in[3];
    const float* br     = (const float*)d_in[4];
    const float* Wc     = (const float*)d_in[5];
    const float* bc     = (const float*)d_in[6];
    const float* Wo     = (const float*)d_in[7];
    const float* bo     = (const float*)d_in[8];

    float* out      = (float*)d_out;
    float* qcol_out = out + (size_t)BB*SS*DD;
    float* val_out  = qcol_out + (size_t)QCOL_ELEMS;

    float *qrow_ptr = nullptr, *merged_ptr = nullptr;
    cudaGetSymbolAddress((void**)&qrow_ptr, g_qrow);
    cudaGetSymbolAddress((void**)&merged_ptr, g_merged);

    cudaFuncSetAttribute(attn_mma, cudaFuncAttributeMaxDynamicSharedMemorySize, ATTN_SMEM);

    dim3 gg(DD/128, NTOK/128);   // 8 x 32
    gemm_tf32<0,1><<<gg, 256>>>(x, Wr, br, qrow_ptr);   // q_row: tf32-rounded downstream anyway
    gemm_tf32<0,3><<<gg, 256>>>(x, Wc, bc, qcol_out);   // q_col: direct output -> 3-pass
    values_kernel<<<QCOL_ELEMS/4/256, 256>>>(x, val_out);

    dim3 ga(SS/128, BB*HH);      // 16 x 32
    attn_mma<<<ga, 256, ATTN_SMEM>>>(x, past_q, past_v, qcol_out, qrow_ptr, merged_ptr);

    gemm_tf32<1,3><<<gg, 256>>>(merged_ptr, Wo, bo, out);  // final output -> 3-pass
}